// round 5
// baseline (speedup 1.0000x reference)
#include <cuda_runtime.h>
#include <math.h>

#define BB 128
#define RR 4096
#define DD 256
#define EPS_NORM 1e-12f
#define EPS_SUM  1e-8f

// scratch: sims[b][r]  (2 MB, static device array — no allocation allowed)
__device__ float g_sims[BB * RR];

// ---------------------------------------------------------------------------
// Pass A: fused copy (reps -> out) + cosine similarity vs. query row.
// grid = (32, B), block = 256 threads (8 warps). Each block handles 128 rows.
// Each warp processes TWO rows per iteration (r, r+8), front-batching
// 4 independent LDG.128 per warp to raise MLP before the reduction chains.
// ---------------------------------------------------------------------------
__global__ void __launch_bounds__(256, 8)
pass_copy_sims(const float* __restrict__ reps,
               const int* __restrict__ qrels,
               float* __restrict__ out)
{
    const int b    = blockIdx.y;
    const int tid  = threadIdx.x;
    const int lane = tid & 31;
    const int warp = tid >> 5;

    __shared__ float qsh[DD];
    __shared__ float red[8];
    __shared__ float s_inv_qn;

    const int    qidx = qrels[b] & (RR - 1);   // int32 input; clamp defensively
    const size_t base = (size_t)b * RR * DD;

    // load query row into shared, compute 1/max(||q||, eps)
    float qv = reps[base + (size_t)qidx * DD + tid];
    qsh[tid] = qv;
    float ss = qv * qv;
    #pragma unroll
    for (int o = 16; o; o >>= 1) ss += __shfl_xor_sync(0xffffffffu, ss, o);
    if (lane == 0) red[warp] = ss;
    __syncthreads();
    if (warp == 0) {
        float v = (lane < 8) ? red[lane] : 0.0f;
        #pragma unroll
        for (int o = 4; o; o >>= 1) v += __shfl_xor_sync(0xffffffffu, v, o);
        if (lane == 0) s_inv_qn = 1.0f / fmaxf(sqrtf(v), EPS_NORM);
    }
    __syncthreads();
    const float iqn = s_inv_qn;

    const int rows_per_block = RR / gridDim.x;          // 128
    const int row0 = blockIdx.x * rows_per_block;

    // two rows per iteration: r and r+8 (8 warps -> stride 16 rows/iter)
    for (int r = row0 + warp; r < row0 + rows_per_block; r += 16) {
        const int r2 = r + 8;
        const float4* src0 = (const float4*)(reps + base + (size_t)r  * DD);
        const float4* src1 = (const float4*)(reps + base + (size_t)r2 * DD);
        float4*       dst0 = (float4*)(out  + base + (size_t)r  * DD);
        float4*       dst1 = (float4*)(out  + base + (size_t)r2 * DD);

        // front-batch 4 independent 16B loads
        float4 a0 = src0[lane];
        float4 c0 = src0[lane + 32];
        float4 a1 = src1[lane];
        float4 c1 = src1[lane + 32];

        dst0[lane]      = a0;
        dst0[lane + 32] = c0;
        dst1[lane]      = a1;
        dst1[lane + 32] = c1;

        const int j = lane * 4;
        const float q0 = qsh[j],       q1 = qsh[j + 1],
                    q2 = qsh[j + 2],   q3 = qsh[j + 3],
                    q4 = qsh[j + 128], q5 = qsh[j + 129],
                    q6 = qsh[j + 130], q7 = qsh[j + 131];

        float dot0 = a0.x*q0 + a0.y*q1 + a0.z*q2 + a0.w*q3
                   + c0.x*q4 + c0.y*q5 + c0.z*q6 + c0.w*q7;
        float s20  = a0.x*a0.x + a0.y*a0.y + a0.z*a0.z + a0.w*a0.w
                   + c0.x*c0.x + c0.y*c0.y + c0.z*c0.z + c0.w*c0.w;
        float dot1 = a1.x*q0 + a1.y*q1 + a1.z*q2 + a1.w*q3
                   + c1.x*q4 + c1.y*q5 + c1.z*q6 + c1.w*q7;
        float s21  = a1.x*a1.x + a1.y*a1.y + a1.z*a1.z + a1.w*a1.w
                   + c1.x*c1.x + c1.y*c1.y + c1.z*c1.z + c1.w*c1.w;

        // interleaved independent shuffle trees
        #pragma unroll
        for (int o = 16; o; o >>= 1) {
            dot0 += __shfl_xor_sync(0xffffffffu, dot0, o);
            s20  += __shfl_xor_sync(0xffffffffu, s20,  o);
            dot1 += __shfl_xor_sync(0xffffffffu, dot1, o);
            s21  += __shfl_xor_sync(0xffffffffu, s21,  o);
        }
        if (lane == 0) {
            g_sims[b * RR + r]  = dot0 * iqn / fmaxf(sqrtf(s20), EPS_NORM);
            g_sims[b * RR + r2] = dot1 * iqn / fmaxf(sqrtf(s21), EPS_NORM);
        }
    }
}

// ---------------------------------------------------------------------------
// Pass B: per-sample masked softmax + weighted row update.
// grid = B, block = 256 threads. Each thread owns 16 sims (strided) and
// output dim `tid`. Valid (masked) indices are compacted into shared and
// only those rows are re-read from global.
// ---------------------------------------------------------------------------
__global__ void __launch_bounds__(256, 1)
pass_update(const float* __restrict__ reps,
            const int* __restrict__ qrels,
            const float* __restrict__ thr_raw,
            const float* __restrict__ str_raw,
            const float* __restrict__ wscale_p,
            const float* __restrict__ temp_p,
            float* __restrict__ out)
{
    const int b   = blockIdx.x;
    const int tid = threadIdx.x;
    const int lane = tid & 31;
    const int warp = tid >> 5;

    const float threshold = 1.0f / (1.0f + expf(-thr_raw[0]));
    const float strength  = 0.2f / (1.0f + expf(-str_raw[0]));
    const float wscale    = wscale_p[0];
    const float temp      = fminf(fmaxf(temp_p[0], 0.1f), 10.0f);

    const int    qidx = qrels[b] & (RR - 1);
    const size_t base = (size_t)b * RR * DD;

    __shared__ float red[8];
    __shared__ float s_bcast;
    __shared__ int   s_cnt;
    __shared__ int   sidx[RR];    // 16 KB
    __shared__ float scoef[RR];   // 16 KB

    if (tid == 0) s_cnt = 0;

    // load 16 sims per thread, apply self-exclusion
    float sl[16];
    float mx = -INFINITY;
    #pragma unroll
    for (int k = 0; k < 16; k++) {
        const int i = tid + 256 * k;
        float s = g_sims[b * RR + i];
        if (i == qidx) s = -1.0f;
        sl[k] = s;
        if (s > threshold) mx = fmaxf(mx, s);
    }

    // block-reduce max over masked entries
    #pragma unroll
    for (int o = 16; o; o >>= 1) mx = fmaxf(mx, __shfl_xor_sync(0xffffffffu, mx, o));
    if (lane == 0) red[warp] = mx;
    __syncthreads();
    if (warp == 0) {
        float v = (lane < 8) ? red[lane] : -INFINITY;
        #pragma unroll
        for (int o = 4; o; o >>= 1) v = fmaxf(v, __shfl_xor_sync(0xffffffffu, v, o));
        if (lane == 0) s_bcast = v;
    }
    __syncthreads();
    const float M = s_bcast;
    const bool has_valid = (M > -INFINITY);

    if (has_valid) {
        // softmax denominator over masked entries: exp((s - M)/temp)
        float dl = 0.0f;
        #pragma unroll
        for (int k = 0; k < 16; k++)
            if (sl[k] > threshold) dl += expf((sl[k] - M) / temp);
        #pragma unroll
        for (int o = 16; o; o >>= 1) dl += __shfl_xor_sync(0xffffffffu, dl, o);
        if (lane == 0) red[warp] = dl;
        __syncthreads();
        if (warp == 0) {
            float v = (lane < 8) ? red[lane] : 0.0f;
            #pragma unroll
            for (int o = 4; o; o >>= 1) v += __shfl_xor_sync(0xffffffffu, v, o);
            if (lane == 0) s_bcast = v;
        }
        __syncthreads();
        const float denom = s_bcast;

        // sum of adjusted (pre-normalization)
        float Sl = 0.0f;
        #pragma unroll
        for (int k = 0; k < 16; k++) {
            const float s = sl[k];
            if (s > threshold) {
                const float w    = expf((s - M) / temp) / denom;
                const float sigw = 1.0f / (1.0f + expf(-10.0f * (s - threshold)));
                Sl += w * sigw * (1.0f + wscale * s);
            }
        }
        #pragma unroll
        for (int o = 16; o; o >>= 1) Sl += __shfl_xor_sync(0xffffffffu, Sl, o);
        if (lane == 0) red[warp] = Sl;
        __syncthreads();
        if (warp == 0) {
            float v = (lane < 8) ? red[lane] : 0.0f;
            #pragma unroll
            for (int o = 4; o; o >>= 1) v += __shfl_xor_sync(0xffffffffu, v, o);
            if (lane == 0) s_bcast = v;
        }
        __syncthreads();
        const float inv_adj_sum = 1.0f / (s_bcast + EPS_SUM);

        // compact valid entries (index + final coefficient)
        #pragma unroll
        for (int k = 0; k < 16; k++) {
            const float s = sl[k];
            if (s > threshold) {
                const int   i    = tid + 256 * k;
                const float w    = expf((s - M) / temp) / denom;
                const float sigw = 1.0f / (1.0f + expf(-10.0f * (s - threshold)));
                const float adj  = w * sigw * (1.0f + wscale * s) * inv_adj_sum;
                const int pos = atomicAdd(&s_cnt, 1);
                sidx[pos]  = i;
                scoef[pos] = adj;
            }
        }
    }
    __syncthreads();

    const int cnt = s_cnt;
    // query row was already copied verbatim by pass A; read it from `out`
    const float qv = out[base + (size_t)qidx * DD + tid];
    float res = qv;
    if (cnt > 0) {
        float wacc = 0.0f;
        for (int k = 0; k < cnt; k++)
            wacc += scoef[k] * reps[base + (size_t)sidx[k] * DD + tid];
        res = (1.0f - strength) * qv + strength * wacc;
    }
    out[base + (size_t)qidx * DD + tid] = res;
}

// ---------------------------------------------------------------------------
extern "C" void kernel_launch(void* const* d_in, const int* in_sizes, int n_in,
                              void* d_out, int out_size)
{
    const float* reps   = (const float*)d_in[0];
    const int*   qrels  = (const int*)d_in[1];     // int32 (JAX x64 disabled)
    const float* thr    = (const float*)d_in[2];
    const float* str    = (const float*)d_in[3];
    const float* wscale = (const float*)d_in[4];
    const float* temp   = (const float*)d_in[5];
    float*       out    = (float*)d_out;

    pass_copy_sims<<<dim3(32, BB), 256>>>(reps, qrels, out);
    pass_update<<<BB, 256>>>(reps, qrels, thr, str, wscale, temp, out);
}

// round 10
// speedup vs baseline: 1.0198x; 1.0198x over previous
#include <cuda_runtime.h>
#include <math.h>

#define BB 128
#define RR 4096
#define DD 256
#define EPS_NORM 1e-12f
#define EPS_SUM  1e-8f

// scratch: sims[b][r]  (2 MB, static device array — no allocation allowed)
__device__ __align__(16) float g_sims[BB * RR];

// ---------------------------------------------------------------------------
// Pass A: fused copy (reps -> out) + cosine similarity vs. query row.
// grid = (32, B), block = 256 threads (8 warps). Each block handles 128 rows.
// Each warp processes TWO rows per iteration (r, r+8), front-batching
// 4 independent LDG.128 per warp. No occupancy cap -> 64-reg budget, no
// spills; streaming hints (ldcs/stcs) since the stream has zero reuse.
// ---------------------------------------------------------------------------
__global__ void __launch_bounds__(256)
pass_copy_sims(const float* __restrict__ reps,
               const int* __restrict__ qrels,
               float* __restrict__ out)
{
    const int b    = blockIdx.y;
    const int tid  = threadIdx.x;
    const int lane = tid & 31;
    const int warp = tid >> 5;

    __shared__ float qsh[DD];
    __shared__ float red[8];
    __shared__ float s_inv_qn;

    const int    qidx = qrels[b] & (RR - 1);   // int32 input; clamp defensively
    const size_t base = (size_t)b * RR * DD;

    // load query row into shared, compute 1/max(||q||, eps)
    float qv = reps[base + (size_t)qidx * DD + tid];
    qsh[tid] = qv;
    float ss = qv * qv;
    #pragma unroll
    for (int o = 16; o; o >>= 1) ss += __shfl_xor_sync(0xffffffffu, ss, o);
    if (lane == 0) red[warp] = ss;
    __syncthreads();
    if (warp == 0) {
        float v = (lane < 8) ? red[lane] : 0.0f;
        #pragma unroll
        for (int o = 4; o; o >>= 1) v += __shfl_xor_sync(0xffffffffu, v, o);
        if (lane == 0) s_inv_qn = 1.0f / fmaxf(sqrtf(v), EPS_NORM);
    }
    __syncthreads();
    const float iqn = s_inv_qn;

    const int rows_per_block = RR / gridDim.x;          // 128
    const int row0 = blockIdx.x * rows_per_block;

    // two rows per iteration: r and r+8 (8 warps -> stride 16 rows/iter)
    for (int r = row0 + warp; r < row0 + rows_per_block; r += 16) {
        const int r2 = r + 8;
        const float4* src0 = (const float4*)(reps + base + (size_t)r  * DD);
        const float4* src1 = (const float4*)(reps + base + (size_t)r2 * DD);
        float4*       dst0 = (float4*)(out  + base + (size_t)r  * DD);
        float4*       dst1 = (float4*)(out  + base + (size_t)r2 * DD);

        // front-batch 4 independent 16B streaming loads
        float4 a0 = __ldcs(src0 + lane);
        float4 c0 = __ldcs(src0 + lane + 32);
        float4 a1 = __ldcs(src1 + lane);
        float4 c1 = __ldcs(src1 + lane + 32);

        __stcs(dst0 + lane,      a0);
        __stcs(dst0 + lane + 32, c0);
        __stcs(dst1 + lane,      a1);
        __stcs(dst1 + lane + 32, c1);

        const int j = lane * 4;
        const float q0 = qsh[j],       q1 = qsh[j + 1],
                    q2 = qsh[j + 2],   q3 = qsh[j + 3],
                    q4 = qsh[j + 128], q5 = qsh[j + 129],
                    q6 = qsh[j + 130], q7 = qsh[j + 131];

        float dot0 = a0.x*q0 + a0.y*q1 + a0.z*q2 + a0.w*q3
                   + c0.x*q4 + c0.y*q5 + c0.z*q6 + c0.w*q7;
        float s20  = a0.x*a0.x + a0.y*a0.y + a0.z*a0.z + a0.w*a0.w
                   + c0.x*c0.x + c0.y*c0.y + c0.z*c0.z + c0.w*c0.w;
        float dot1 = a1.x*q0 + a1.y*q1 + a1.z*q2 + a1.w*q3
                   + c1.x*q4 + c1.y*q5 + c1.z*q6 + c1.w*q7;
        float s21  = a1.x*a1.x + a1.y*a1.y + a1.z*a1.z + a1.w*a1.w
                   + c1.x*c1.x + c1.y*c1.y + c1.z*c1.z + c1.w*c1.w;

        // interleaved independent shuffle trees
        #pragma unroll
        for (int o = 16; o; o >>= 1) {
            dot0 += __shfl_xor_sync(0xffffffffu, dot0, o);
            s20  += __shfl_xor_sync(0xffffffffu, s20,  o);
            dot1 += __shfl_xor_sync(0xffffffffu, dot1, o);
            s21  += __shfl_xor_sync(0xffffffffu, s21,  o);
        }
        if (lane == 0) {
            g_sims[b * RR + r]  = dot0 * iqn / fmaxf(sqrtf(s20), EPS_NORM);
            g_sims[b * RR + r2] = dot1 * iqn / fmaxf(sqrtf(s21), EPS_NORM);
        }
    }
}

// ---------------------------------------------------------------------------
// Pass B: per-sample masked softmax + weighted row update.
// grid = B, block = 256 threads. Each thread owns 16 sims (4 x float4) and
// output dim `tid`. Valid (masked) indices are compacted into shared and
// only those rows are re-read from global.
// ---------------------------------------------------------------------------
__global__ void __launch_bounds__(256, 1)
pass_update(const float* __restrict__ reps,
            const int* __restrict__ qrels,
            const float* __restrict__ thr_raw,
            const float* __restrict__ str_raw,
            const float* __restrict__ wscale_p,
            const float* __restrict__ temp_p,
            float* __restrict__ out)
{
    const int b   = blockIdx.x;
    const int tid = threadIdx.x;
    const int lane = tid & 31;
    const int warp = tid >> 5;

    const float threshold = 1.0f / (1.0f + expf(-thr_raw[0]));
    const float strength  = 0.2f / (1.0f + expf(-str_raw[0]));
    const float wscale    = wscale_p[0];
    const float temp      = fminf(fmaxf(temp_p[0], 0.1f), 10.0f);

    const int    qidx = qrels[b] & (RR - 1);
    const size_t base = (size_t)b * RR * DD;

    __shared__ float red[8];
    __shared__ float s_bcast;
    __shared__ int   s_cnt;
    __shared__ int   sidx[RR];    // 16 KB
    __shared__ float scoef[RR];   // 16 KB

    if (tid == 0) s_cnt = 0;

    // load 16 sims per thread as 4 float4s: vec v covers indices
    // (tid + 256*v)*4 + c. Apply self-exclusion inline.
    const float4* sims4 = (const float4*)(g_sims + b * RR);
    float sl[16];
    float mx = -INFINITY;
    #pragma unroll
    for (int v = 0; v < 4; v++) {
        const float4 p = sims4[tid + 256 * v];
        const int i0 = (tid + 256 * v) * 4;
        sl[v*4+0] = (i0 + 0 == qidx) ? -1.0f : p.x;
        sl[v*4+1] = (i0 + 1 == qidx) ? -1.0f : p.y;
        sl[v*4+2] = (i0 + 2 == qidx) ? -1.0f : p.z;
        sl[v*4+3] = (i0 + 3 == qidx) ? -1.0f : p.w;
    }
    #pragma unroll
    for (int k = 0; k < 16; k++)
        if (sl[k] > threshold) mx = fmaxf(mx, sl[k]);

    // block-reduce max over masked entries
    #pragma unroll
    for (int o = 16; o; o >>= 1) mx = fmaxf(mx, __shfl_xor_sync(0xffffffffu, mx, o));
    if (lane == 0) red[warp] = mx;
    __syncthreads();
    if (warp == 0) {
        float v = (lane < 8) ? red[lane] : -INFINITY;
        #pragma unroll
        for (int o = 4; o; o >>= 1) v = fmaxf(v, __shfl_xor_sync(0xffffffffu, v, o));
        if (lane == 0) s_bcast = v;
    }
    __syncthreads();
    const float M = s_bcast;
    const bool has_valid = (M > -INFINITY);

    if (has_valid) {
        // softmax denominator over masked entries: exp((s - M)/temp)
        float dl = 0.0f;
        #pragma unroll
        for (int k = 0; k < 16; k++)
            if (sl[k] > threshold) dl += expf((sl[k] - M) / temp);
        #pragma unroll
        for (int o = 16; o; o >>= 1) dl += __shfl_xor_sync(0xffffffffu, dl, o);
        if (lane == 0) red[warp] = dl;
        __syncthreads();
        if (warp == 0) {
            float v = (lane < 8) ? red[lane] : 0.0f;
            #pragma unroll
            for (int o = 4; o; o >>= 1) v += __shfl_xor_sync(0xffffffffu, v, o);
            if (lane == 0) s_bcast = v;
        }
        __syncthreads();
        const float denom = s_bcast;

        // sum of adjusted (pre-normalization)
        float Sl = 0.0f;
        #pragma unroll
        for (int k = 0; k < 16; k++) {
            const float s = sl[k];
            if (s > threshold) {
                const float w    = expf((s - M) / temp) / denom;
                const float sigw = 1.0f / (1.0f + expf(-10.0f * (s - threshold)));
                Sl += w * sigw * (1.0f + wscale * s);
            }
        }
        #pragma unroll
        for (int o = 16; o; o >>= 1) Sl += __shfl_xor_sync(0xffffffffu, Sl, o);
        if (lane == 0) red[warp] = Sl;
        __syncthreads();
        if (warp == 0) {
            float v = (lane < 8) ? red[lane] : 0.0f;
            #pragma unroll
            for (int o = 4; o; o >>= 1) v += __shfl_xor_sync(0xffffffffu, v, o);
            if (lane == 0) s_bcast = v;
        }
        __syncthreads();
        const float inv_adj_sum = 1.0f / (s_bcast + EPS_SUM);

        // compact valid entries (index + final coefficient)
        #pragma unroll
        for (int k = 0; k < 16; k++) {
            const float s = sl[k];
            if (s > threshold) {
                const int   i    = (tid + 256 * (k >> 2)) * 4 + (k & 3);
                const float w    = expf((s - M) / temp) / denom;
                const float sigw = 1.0f / (1.0f + expf(-10.0f * (s - threshold)));
                const float adj  = w * sigw * (1.0f + wscale * s) * inv_adj_sum;
                const int pos = atomicAdd(&s_cnt, 1);
                sidx[pos]  = i;
                scoef[pos] = adj;
            }
        }
    }
    __syncthreads();

    const int cnt = s_cnt;
    // query row was already copied verbatim by pass A; read it from `out`
    const float qv = out[base + (size_t)qidx * DD + tid];
    float res = qv;
    if (cnt > 0) {
        float wacc = 0.0f;
        for (int k = 0; k < cnt; k++)
            wacc += scoef[k] * reps[base + (size_t)sidx[k] * DD + tid];
        res = (1.0f - strength) * qv + strength * wacc;
    }
    out[base + (size_t)qidx * DD + tid] = res;
}

// ---------------------------------------------------------------------------
extern "C" void kernel_launch(void* const* d_in, const int* in_sizes, int n_in,
                              void* d_out, int out_size)
{
    const float* reps   = (const float*)d_in[0];
    const int*   qrels  = (const int*)d_in[1];     // int32 (JAX x64 disabled)
    const float* thr    = (const float*)d_in[2];
    const float* str    = (const float*)d_in[3];
    const float* wscale = (const float*)d_in[4];
    const float* temp   = (const float*)d_in[5];
    float*       out    = (float*)d_out;

    pass_copy_sims<<<dim3(32, BB), 256>>>(reps, qrels, out);
    pass_update<<<BB, 256>>>(reps, qrels, thr, str, wscale, temp, out);
}